// round 7
// baseline (speedup 1.0000x reference)
#include <cuda_runtime.h>
#include <cuda_fp16.h>
#include <cstdint>

#define IM 1024
#define NSEG 128
#define BLOCK 256   // render block threads
#define PPT 4       // pixels per thread along y (2 half2 pairs)
#define NPAIR (PPT / 2)
#define RGRID ((IM / BLOCK) * (IM / PPT))   // 4 * 256 = 1024 render blocks
#define NBLOCK 256  // normalize block
#define NF4PT 4     // float4s per normalize thread (MLP)
#define SCALE (1.0f / 64.0f)   // work in 1/64 px units (scale-invariant output)

// Scratch; every slot rewritten per call, ticket wraps to 0 -> no init kernel.
__device__ float g_bmin[RGRID];
__device__ float g_bmax[RGRID];
__device__ float g_min_v;
__device__ float g_scale_v;
__device__ unsigned g_ticket;

struct __align__(16) SegA {     // one LDS.128
    __half2 nx0;   // broadcast(-x0*S)
    __half2 ny0;   // broadcast(-y0*S)
    __half2 dxi;   // broadcast(dx*invd)
    __half2 dyi;   // broadcast(dy*invd)
};
struct __align__(8) SegB {      // one LDS.64
    __half2 ndx;   // broadcast(-dx*S)
    __half2 ndy;   // broadcast(-dy*S)
};

__device__ __forceinline__ float fsqrt_approx(float x) {
    float r; asm("sqrt.approx.f32 %0, %1;" : "=f"(r) : "f"(x)); return r;
}

__global__ void __launch_bounds__(BLOCK)
sk_render_kernel(const float* __restrict__ xs, const float* __restrict__ ys,
                 float* __restrict__ out) {
    __shared__ SegA sA[NSEG];
    __shared__ SegB sB[NSEG];
    __shared__ float s_wmin[BLOCK / 32], s_wmax[BLOCK / 32];
    __shared__ bool s_last;

    const int tid = threadIdx.x;

    if (tid < NSEG) {
        float x0 = xs[tid] * SCALE, x1 = xs[tid + 1] * SCALE;
        float y0 = ys[tid] * SCALE, y1 = ys[tid + 1] * SCALE;
        float dx = x1 - x0;
        float dy = y1 - y0;
        float invd = 1.0f / (fmaf(dx, dx, dy * dy) + 1e-12f);
        SegA a;
        a.nx0 = __float2half2_rn(-x0);
        a.ny0 = __float2half2_rn(-y0);
        a.dxi = __float2half2_rn(dx * invd);
        a.dyi = __float2half2_rn(dy * invd);
        sA[tid] = a;
        SegB b;
        b.ndx = __float2half2_rn(-dx);
        b.ndy = __float2half2_rn(-dy);
        sB[tid] = b;
    }
    __syncthreads();

    // 4 blocks across x (256 cols each), 256 block-rows across y (PPT=4 rows).
    const int bx = blockIdx.x & 3;
    const int by = blockIdx.x >> 2;
    const int x  = bx * BLOCK + tid;
    const int y0i = by * PPT;
    // xp*SCALE = x/64 is exact in fp16 (multiple of 2^-6 with <=10-bit mantissa)
    const __half2 xp2 = __float2half2_rn((float)x * SCALE);

    __half2 yp2[NPAIR];
    float acc[PPT];
#pragma unroll
    for (int p = 0; p < NPAIR; p++) {
        yp2[p] = __floats2half2_rn((float)(y0i + 2 * p) * SCALE,
                                   (float)(y0i + 2 * p + 1) * SCALE);
        acc[2 * p] = 0.0f; acc[2 * p + 1] = 0.0f;
    }

#pragma unroll 2
    for (int k = 0; k < NSEG; k++) {
        const SegA a = sA[k];
        const SegB b = sB[k];
        const __half2 xd = __hadd2(xp2, a.nx0);     // xp - x0
        const __half2 q  = __hmul2(xd, a.dxi);      // (xp-x0)*dx*invd

#pragma unroll
        for (int p = 0; p < NPAIR; p++) {
            __half2 yd = __hadd2(yp2[p], a.ny0);            // yp - y0
            __half2 t  = __hfma2_sat(yd, a.dyi, q);         // clamp(t,0,1)
            __half2 ex = __hfma2(t, b.ndx, xd);             // xp - (x0+t*dx)
            __half2 ey = __hfma2(t, b.ndy, yd);             // yp - (y0+t*dy)
            __half2 dq = __hmul2(ey, ey);
            __half2 d2 = __hfma2(ex, ex, dq);
            // Bit-shift fp16->fp32 reinterpret: result = d2 * 2^-112 EXACTLY
            // (linear in bits for d2 >= 0, denormals included). The uniform
            // 2^-112 factor cancels in the min/max normalization.
            unsigned v;
            __builtin_memcpy(&v, &d2, 4);
            float dl = __uint_as_float((v << 13) & 0x0FFFE000u);
            float dh = __uint_as_float((v >> 3)  & 0x0FFFE000u);
            acc[2 * p]     += fsqrt_approx(dl);
            acc[2 * p + 1] += fsqrt_approx(dh);
        }
    }

    // Write raw sums + block min/max
    float lmin = acc[0], lmax = acc[0];
#pragma unroll
    for (int j = 0; j < PPT; j++) {
        out[(y0i + j) * IM + x] = acc[j];
        lmin = fminf(lmin, acc[j]);
        lmax = fmaxf(lmax, acc[j]);
    }
#pragma unroll
    for (int off = 16; off > 0; off >>= 1) {
        lmin = fminf(lmin, __shfl_xor_sync(0xFFFFFFFFu, lmin, off));
        lmax = fmaxf(lmax, __shfl_xor_sync(0xFFFFFFFFu, lmax, off));
    }
    const int lane = tid & 31;
    const int warp = tid >> 5;
    if (lane == 0) { s_wmin[warp] = lmin; s_wmax[warp] = lmax; }
    __syncthreads();
    if (tid == 0) {
        float bmin = s_wmin[0], bmax = s_wmax[0];
#pragma unroll
        for (int w = 1; w < BLOCK / 32; w++) {
            bmin = fminf(bmin, s_wmin[w]);
            bmax = fmaxf(bmax, s_wmax[w]);
        }
        g_bmin[blockIdx.x] = bmin;
        g_bmax[blockIdx.x] = bmax;
        __threadfence();
        unsigned ticket = atomicInc(&g_ticket, RGRID - 1);  // wraps -> deterministic
        s_last = (ticket == RGRID - 1);
    }
    __syncthreads();

    // Last-arriving block reduces the 1024 (min,max) pairs. Nobody waits on it
    // inside this kernel; the normalize launch is stream-ordered after us.
    if (s_last) {
        __threadfence();
        volatile float* vmin = g_bmin;
        volatile float* vmax = g_bmax;
        float m0 = vmin[tid], m1 = vmax[tid];
#pragma unroll
        for (int i = 1; i < RGRID / BLOCK; i++) {
            m0 = fminf(m0, vmin[tid + i * BLOCK]);
            m1 = fmaxf(m1, vmax[tid + i * BLOCK]);
        }
#pragma unroll
        for (int off = 16; off > 0; off >>= 1) {
            m0 = fminf(m0, __shfl_xor_sync(0xFFFFFFFFu, m0, off));
            m1 = fmaxf(m1, __shfl_xor_sync(0xFFFFFFFFu, m1, off));
        }
        if (lane == 0) { s_wmin[warp] = m0; s_wmax[warp] = m1; }
        __syncthreads();
        if (tid == 0) {
            float bmin = s_wmin[0], bmax = s_wmax[0];
#pragma unroll
            for (int w = 1; w < BLOCK / 32; w++) {
                bmin = fminf(bmin, s_wmin[w]);
                bmax = fmaxf(bmax, s_wmax[w]);
            }
            g_min_v   = bmin;
            g_scale_v = 1.0f / (bmax - bmin);
        }
    }
}

__global__ void __launch_bounds__(NBLOCK)
sk_normalize_kernel(float* __restrict__ out) {
    const float tmin = g_min_v;
    const float sc   = g_scale_v;
    float4* p4 = reinterpret_cast<float4*>(out);
    const int base = blockIdx.x * NBLOCK + threadIdx.x;
    float4 v[NF4PT];
#pragma unroll
    for (int i = 0; i < NF4PT; i++)         // batched loads -> MLP=4
        v[i] = p4[base + i * (NBLOCK * (IM * IM / (4 * NBLOCK * NF4PT)))];
#pragma unroll
    for (int i = 0; i < NF4PT; i++) {
        v[i].x = (v[i].x - tmin) * sc;
        v[i].y = (v[i].y - tmin) * sc;
        v[i].z = (v[i].z - tmin) * sc;
        v[i].w = (v[i].w - tmin) * sc;
        p4[base + i * (NBLOCK * (IM * IM / (4 * NBLOCK * NF4PT)))] = v[i];
    }
}

extern "C" void kernel_launch(void* const* d_in, const int* in_sizes, int n_in,
                              void* d_out, int out_size) {
    const float* xs = (const float*)d_in[0];
    const float* ys = (const float*)d_in[1];
    float* out = (float*)d_out;

    sk_render_kernel<<<RGRID, BLOCK>>>(xs, ys, out);
    // 1M floats / (16 per thread * 256 threads) = 256 blocks
    sk_normalize_kernel<<<(IM * IM) / (4 * NBLOCK * NF4PT), NBLOCK>>>(out);
}

// round 8
// speedup vs baseline: 1.1490x; 1.1490x over previous
#include <cuda_runtime.h>
#include <cuda_fp16.h>
#include <cstdint>

#define IM 1024
#define NSEG 128
#define BLOCK 128   // render block (== NSEG)
#define PPT 8       // pixels per thread along y (4 half2 pairs)
#define NPAIR (PPT / 2)
#define RGRID ((IM / BLOCK) * (IM / PPT))   // 1024 render blocks
#define NBLOCK 256  // normalize block
#define SCALE (1.0f / 64.0f)   // work in 1/64 px units (scale-invariant output)

// Scratch; fully rewritten each call, ticket wraps to 0 -> no init kernel.
__device__ float g_bmin[RGRID];
__device__ float g_bmax[RGRID];
__device__ float g_min_v;
__device__ float g_scale_v;
__device__ unsigned g_ticket;

struct __align__(16) SegA {     // one LDS.128 (broadcast)
    __half2 nx0;   // broadcast(-x0*S)
    __half2 ny0;   // broadcast(-y0*S)
    __half2 dxi;   // broadcast(dx*invd)
    __half2 dyi;   // broadcast(dy*invd)
};
struct __align__(8) SegB {      // one LDS.64 (broadcast)
    __half2 ndx;   // broadcast(-dx*S)
    __half2 ndy;   // broadcast(-dy*S)
};

__global__ void __launch_bounds__(BLOCK)
sk_render_kernel(const float* __restrict__ xs, const float* __restrict__ ys,
                 float* __restrict__ out) {
    __shared__ SegA sA[NSEG];
    __shared__ SegB sB[NSEG];
    __shared__ float s_wmin[BLOCK / 32], s_wmax[BLOCK / 32];
    __shared__ bool s_last;

    const int tid = threadIdx.x;

    {
        float x0 = xs[tid] * SCALE, x1 = xs[tid + 1] * SCALE;
        float y0 = ys[tid] * SCALE, y1 = ys[tid + 1] * SCALE;
        float dx = x1 - x0;
        float dy = y1 - y0;
        float invd = 1.0f / (fmaf(dx, dx, dy * dy) + 1e-12f);
        SegA a;
        a.nx0 = __float2half2_rn(-x0);
        a.ny0 = __float2half2_rn(-y0);
        a.dxi = __float2half2_rn(dx * invd);
        a.dyi = __float2half2_rn(dy * invd);
        sA[tid] = a;
        SegB b;
        b.ndx = __float2half2_rn(-dx);
        b.ndy = __float2half2_rn(-dy);
        sB[tid] = b;
    }
    __syncthreads();

    // 8 blocks across x (128 cols), 128 block-rows across y (PPT=8 rows).
    const int bx = blockIdx.x & 7;
    const int by = blockIdx.x >> 3;
    const int x  = bx * BLOCK + tid;
    const int y0i = by * PPT;
    // x*SCALE = x/64 is exact in fp16 (multiple of 2^-6, <=10-bit mantissa)
    const __half2 xp2 = __float2half2_rn((float)x * SCALE);

    __half2 yp2[NPAIR];
    float acc[PPT];
#pragma unroll
    for (int p = 0; p < NPAIR; p++) {
        yp2[p] = __floats2half2_rn((float)(y0i + 2 * p) * SCALE,
                                   (float)(y0i + 2 * p + 1) * SCALE);
        acc[2 * p] = 0.0f; acc[2 * p + 1] = 0.0f;
    }

#pragma unroll 4
    for (int k = 0; k < NSEG; k++) {
        const SegA a = sA[k];
        const SegB b = sB[k];
        const __half2 xd = __hadd2(xp2, a.nx0);     // xp - x0
        const __half2 q  = __hmul2(xd, a.dxi);      // (xp-x0)*dx*invd

#pragma unroll
        for (int p = 0; p < NPAIR; p++) {
            __half2 yd = __hadd2(yp2[p], a.ny0);            // yp - y0
            __half2 t  = __hfma2_sat(yd, a.dyi, q);         // clamp(t,0,1)
            __half2 ex = __hfma2(t, b.ndx, xd);             // xp - (x0+t*dx)
            __half2 ey = __hfma2(t, b.ndy, yd);             // yp - (y0+t*dy)
            __half2 dq = __hmul2(ey, ey);
            __half2 d2 = __hfma2(ex, ex, dq);
            __half2 d  = h2sqrt(d2);                        // packed sqrt (XU x1)
            // Bit-expand fp16->fp32: value becomes d * 2^-112 EXACTLY
            // (linear reinterpret for d >= 0, denormals included). The uniform
            // 2^-112 factor cancels in the min/max normalization.
            unsigned v;
            __builtin_memcpy(&v, &d, 4);
            float dl = __uint_as_float((v << 13) & 0x0FFFE000u);
            float dh = __uint_as_float((v >> 3)  & 0x0FFFE000u);
            acc[2 * p]     += dl;
            acc[2 * p + 1] += dh;
        }
    }

    // Write raw sums + block min/max
    float lmin = acc[0], lmax = acc[0];
#pragma unroll
    for (int j = 0; j < PPT; j++) {
        out[(y0i + j) * IM + x] = acc[j];
        lmin = fminf(lmin, acc[j]);
        lmax = fmaxf(lmax, acc[j]);
    }
#pragma unroll
    for (int off = 16; off > 0; off >>= 1) {
        lmin = fminf(lmin, __shfl_xor_sync(0xFFFFFFFFu, lmin, off));
        lmax = fmaxf(lmax, __shfl_xor_sync(0xFFFFFFFFu, lmax, off));
    }
    const int lane = tid & 31;
    const int warp = tid >> 5;
    if (lane == 0) { s_wmin[warp] = lmin; s_wmax[warp] = lmax; }
    __syncthreads();
    if (tid == 0) {
        float bmin = s_wmin[0], bmax = s_wmax[0];
#pragma unroll
        for (int w = 1; w < BLOCK / 32; w++) {
            bmin = fminf(bmin, s_wmin[w]);
            bmax = fmaxf(bmax, s_wmax[w]);
        }
        g_bmin[blockIdx.x] = bmin;
        g_bmax[blockIdx.x] = bmax;
        __threadfence();
        unsigned ticket = atomicInc(&g_ticket, RGRID - 1);  // wraps -> deterministic
        s_last = (ticket == RGRID - 1);
    }
    __syncthreads();

    // Last-arriving block reduces the 1024 (min,max) pairs; normalize launch
    // is stream-ordered after us, so nobody waits in-kernel.
    if (s_last) {
        __threadfence();
        volatile float* vmin = g_bmin;
        volatile float* vmax = g_bmax;
        float m0 = vmin[tid], m1 = vmax[tid];
#pragma unroll
        for (int i = 1; i < RGRID / BLOCK; i++) {
            m0 = fminf(m0, vmin[tid + i * BLOCK]);
            m1 = fmaxf(m1, vmax[tid + i * BLOCK]);
        }
#pragma unroll
        for (int off = 16; off > 0; off >>= 1) {
            m0 = fminf(m0, __shfl_xor_sync(0xFFFFFFFFu, m0, off));
            m1 = fmaxf(m1, __shfl_xor_sync(0xFFFFFFFFu, m1, off));
        }
        if (lane == 0) { s_wmin[warp] = m0; s_wmax[warp] = m1; }
        __syncthreads();
        if (tid == 0) {
            float bmin = s_wmin[0], bmax = s_wmax[0];
#pragma unroll
            for (int w = 1; w < BLOCK / 32; w++) {
                bmin = fminf(bmin, s_wmin[w]);
                bmax = fmaxf(bmax, s_wmax[w]);
            }
            g_min_v   = bmin;
            g_scale_v = 1.0f / (bmax - bmin);
        }
    }
}

__global__ void __launch_bounds__(NBLOCK)
sk_normalize_kernel(float* __restrict__ out) {
    const float tmin = g_min_v;
    const float sc   = g_scale_v;
    const int i = blockIdx.x * NBLOCK + threadIdx.x;  // one float4 per thread
    float4* p = reinterpret_cast<float4*>(out) + i;
    float4 v = *p;
    v.x = (v.x - tmin) * sc;
    v.y = (v.y - tmin) * sc;
    v.z = (v.z - tmin) * sc;
    v.w = (v.w - tmin) * sc;
    *p = v;
}

extern "C" void kernel_launch(void* const* d_in, const int* in_sizes, int n_in,
                              void* d_out, int out_size) {
    const float* xs = (const float*)d_in[0];
    const float* ys = (const float*)d_in[1];
    float* out = (float*)d_out;

    sk_render_kernel<<<RGRID, BLOCK>>>(xs, ys, out);
    // 1M floats / (4 per thread * 256 threads) = 1024 blocks
    sk_normalize_kernel<<<(IM * IM) / (4 * NBLOCK), NBLOCK>>>(out);
}

// round 9
// speedup vs baseline: 1.3004x; 1.1317x over previous
#include <cuda_runtime.h>
#include <cuda_fp16.h>
#include <cstdint>

#define IM 1024
#define NSEG 128
#define BLOCK 128   // render block (== NSEG)
#define PPT 8       // pixels per thread along y (4 half2 pairs)
#define NPAIR (PPT / 2)
#define CHUNK 8     // segments per half2-accumulation chunk (precision guard)
#define RGRID ((IM / BLOCK) * (IM / PPT))   // 1024 render blocks
#define NBLOCK 256  // normalize block
#define SCALE (1.0f / 64.0f)   // work in 1/64 px units (scale-invariant output)

// Scratch; fully rewritten each call, ticket wraps to 0 -> no init kernel.
__device__ float g_bmin[RGRID];
__device__ float g_bmax[RGRID];
__device__ float g_min_v;
__device__ float g_scale_v;
__device__ unsigned g_ticket;

struct __align__(16) SegA {     // one LDS.128 (broadcast)
    __half2 nx0;   // broadcast(-x0*S)
    __half2 ny0;   // broadcast(-y0*S)
    __half2 dxi;   // broadcast(dx*invd)
    __half2 dyi;   // broadcast(dy*invd)
};
struct __align__(8) SegB {      // one LDS.64 (broadcast)
    __half2 ndx;   // broadcast(-dx*S)
    __half2 ndy;   // broadcast(-dy*S)
};

__global__ void __launch_bounds__(BLOCK)
sk_render_kernel(const float* __restrict__ xs, const float* __restrict__ ys,
                 float* __restrict__ out) {
    __shared__ SegA sA[NSEG];
    __shared__ SegB sB[NSEG];
    __shared__ float s_wmin[BLOCK / 32], s_wmax[BLOCK / 32];
    __shared__ bool s_last;

    const int tid = threadIdx.x;

    {
        float x0 = xs[tid] * SCALE, x1 = xs[tid + 1] * SCALE;
        float y0 = ys[tid] * SCALE, y1 = ys[tid + 1] * SCALE;
        float dx = x1 - x0;
        float dy = y1 - y0;
        float invd = 1.0f / (fmaf(dx, dx, dy * dy) + 1e-12f);
        SegA a;
        a.nx0 = __float2half2_rn(-x0);
        a.ny0 = __float2half2_rn(-y0);
        a.dxi = __float2half2_rn(dx * invd);
        a.dyi = __float2half2_rn(dy * invd);
        sA[tid] = a;
        SegB b;
        b.ndx = __float2half2_rn(-dx);
        b.ndy = __float2half2_rn(-dy);
        sB[tid] = b;
    }
    __syncthreads();

    // 8 blocks across x (128 cols), 128 block-rows across y (PPT=8 rows).
    const int bx = blockIdx.x & 7;
    const int by = blockIdx.x >> 3;
    const int x  = bx * BLOCK + tid;
    const int y0i = by * PPT;
    // x*SCALE = x/64 is exact in fp16 (multiple of 2^-6, <=10-bit mantissa)
    const __half2 xp2 = __float2half2_rn((float)x * SCALE);

    __half2 yp2[NPAIR];
    float acc[PPT];
#pragma unroll
    for (int p = 0; p < NPAIR; p++) {
        yp2[p] = __floats2half2_rn((float)(y0i + 2 * p) * SCALE,
                                   (float)(y0i + 2 * p + 1) * SCALE);
        acc[2 * p] = 0.0f; acc[2 * p + 1] = 0.0f;
    }

    const __half2 hzero = __float2half2_rn(0.0f);

#pragma unroll 2
    for (int kc = 0; kc < NSEG / CHUNK; kc++) {
        __half2 hacc[NPAIR];
#pragma unroll
        for (int p = 0; p < NPAIR; p++) hacc[p] = hzero;

#pragma unroll
        for (int kk = 0; kk < CHUNK; kk++) {
            const int k = kc * CHUNK + kk;
            const SegA a = sA[k];
            const SegB b = sB[k];
            const __half2 xd = __hadd2(xp2, a.nx0);     // xp - x0
            const __half2 q  = __hmul2(xd, a.dxi);      // (xp-x0)*dx*invd

#pragma unroll
            for (int p = 0; p < NPAIR; p++) {
                __half2 yd = __hadd2(yp2[p], a.ny0);            // yp - y0
                __half2 t  = __hfma2_sat(yd, a.dyi, q);         // clamp(t,0,1)
                __half2 ex = __hfma2(t, b.ndx, xd);             // xp - (x0+t*dx)
                __half2 ey = __hfma2(t, b.ndy, yd);             // yp - (y0+t*dy)
                __half2 dq = __hmul2(ey, ey);
                __half2 d2 = __hfma2(ex, ex, dq);
                hacc[p] = __hadd2(hacc[p], h2sqrt(d2));         // half2 accumulate
            }
        }

        // Flush chunk: bit-expand fp16->fp32 (value * 2^-112 EXACTLY; uniform
        // factor cancels in min/max normalization), add into fp32 accumulators.
#pragma unroll
        for (int p = 0; p < NPAIR; p++) {
            unsigned v;
            __builtin_memcpy(&v, &hacc[p], 4);
            acc[2 * p]     += __uint_as_float((v << 13) & 0x0FFFE000u);
            acc[2 * p + 1] += __uint_as_float((v >> 3)  & 0x0FFFE000u);
        }
    }

    // Write raw sums + block min/max
    float lmin = acc[0], lmax = acc[0];
#pragma unroll
    for (int j = 0; j < PPT; j++) {
        out[(y0i + j) * IM + x] = acc[j];
        lmin = fminf(lmin, acc[j]);
        lmax = fmaxf(lmax, acc[j]);
    }
#pragma unroll
    for (int off = 16; off > 0; off >>= 1) {
        lmin = fminf(lmin, __shfl_xor_sync(0xFFFFFFFFu, lmin, off));
        lmax = fmaxf(lmax, __shfl_xor_sync(0xFFFFFFFFu, lmax, off));
    }
    const int lane = tid & 31;
    const int warp = tid >> 5;
    if (lane == 0) { s_wmin[warp] = lmin; s_wmax[warp] = lmax; }
    __syncthreads();
    if (tid == 0) {
        float bmin = s_wmin[0], bmax = s_wmax[0];
#pragma unroll
        for (int w = 1; w < BLOCK / 32; w++) {
            bmin = fminf(bmin, s_wmin[w]);
            bmax = fmaxf(bmax, s_wmax[w]);
        }
        g_bmin[blockIdx.x] = bmin;
        g_bmax[blockIdx.x] = bmax;
        __threadfence();
        unsigned ticket = atomicInc(&g_ticket, RGRID - 1);  // wraps -> deterministic
        s_last = (ticket == RGRID - 1);
    }
    __syncthreads();

    // Last-arriving block reduces the 1024 (min,max) pairs; normalize launch
    // is stream-ordered after us.
    if (s_last) {
        __threadfence();
        volatile float* vmin = g_bmin;
        volatile float* vmax = g_bmax;
        float m0 = vmin[tid], m1 = vmax[tid];
#pragma unroll
        for (int i = 1; i < RGRID / BLOCK; i++) {
            m0 = fminf(m0, vmin[tid + i * BLOCK]);
            m1 = fmaxf(m1, vmax[tid + i * BLOCK]);
        }
#pragma unroll
        for (int off = 16; off > 0; off >>= 1) {
            m0 = fminf(m0, __shfl_xor_sync(0xFFFFFFFFu, m0, off));
            m1 = fmaxf(m1, __shfl_xor_sync(0xFFFFFFFFu, m1, off));
        }
        if (lane == 0) { s_wmin[warp] = m0; s_wmax[warp] = m1; }
        __syncthreads();
        if (tid == 0) {
            float bmin = s_wmin[0], bmax = s_wmax[0];
#pragma unroll
            for (int w = 1; w < BLOCK / 32; w++) {
                bmin = fminf(bmin, s_wmin[w]);
                bmax = fmaxf(bmax, s_wmax[w]);
            }
            g_min_v   = bmin;
            g_scale_v = 1.0f / (bmax - bmin);
        }
    }
}

__global__ void __launch_bounds__(NBLOCK)
sk_normalize_kernel(float* __restrict__ out) {
    const float tmin = g_min_v;
    const float sc   = g_scale_v;
    const int i = (blockIdx.x * NBLOCK + threadIdx.x) * 2;  // two float4/thread
    float4* p = reinterpret_cast<float4*>(out) + i;
    float4 v0 = p[0];
    float4 v1 = p[1];
    v0.x = (v0.x - tmin) * sc;  v0.y = (v0.y - tmin) * sc;
    v0.z = (v0.z - tmin) * sc;  v0.w = (v0.w - tmin) * sc;
    v1.x = (v1.x - tmin) * sc;  v1.y = (v1.y - tmin) * sc;
    v1.z = (v1.z - tmin) * sc;  v1.w = (v1.w - tmin) * sc;
    p[0] = v0;
    p[1] = v1;
}

extern "C" void kernel_launch(void* const* d_in, const int* in_sizes, int n_in,
                              void* d_out, int out_size) {
    const float* xs = (const float*)d_in[0];
    const float* ys = (const float*)d_in[1];
    float* out = (float*)d_out;

    sk_render_kernel<<<RGRID, BLOCK>>>(xs, ys, out);
    // 1M floats / (8 per thread * 256 threads) = 512 blocks
    sk_normalize_kernel<<<(IM * IM) / (8 * NBLOCK), NBLOCK>>>(out);
}